// round 15
// baseline (speedup 1.0000x reference)
#include <cuda_runtime.h>
#include <cstdint>
#include <math.h>

// ---------------------------------------------------------------------------
// MultiHeadAttention. QKV/QKT/AV: tf32 mma.sync path (R14 config).
// PROJ: bf16x2 split-precision probe (m16n8k16, 3-term, fp32 accumulate).
// d_out = y [S,F] then attn [8,S,S] (fp32). S=4096, F=H=1024, dk=128.
// ---------------------------------------------------------------------------

#define SMAX 4096
#define HMAX 1024
#define NHEAD 8

__device__ float g_qkv[3 * SMAX * HMAX];     // q | k | (v unused plane)
__device__ float g_vt[HMAX * SMAX];          // v transposed [H][S]
__device__ float g_y[SMAX * HMAX];
__device__ float g_rs[NHEAD * SMAX];         // raw row sums of exp

__device__ __forceinline__ unsigned tf32u(unsigned x) {
    unsigned r;
    asm("cvt.rna.tf32.f32 %0, %1;" : "=r"(r) : "f"(__uint_as_float(x)));
    return r;
}
__device__ __forceinline__ float tf32f(float x) {
    unsigned r;
    asm("cvt.rna.tf32.f32 %0, %1;" : "=r"(r) : "f"(x));
    return __uint_as_float(r);
}
__device__ __forceinline__ void mma_tf32(float* c, const unsigned* a, const unsigned* b) {
    asm volatile(
        "mma.sync.aligned.m16n8k8.row.col.f32.tf32.tf32.f32 "
        "{%0,%1,%2,%3}, {%4,%5,%6,%7}, {%8,%9}, {%0,%1,%2,%3};"
        : "+f"(c[0]), "+f"(c[1]), "+f"(c[2]), "+f"(c[3])
        : "r"(a[0]), "r"(a[1]), "r"(a[2]), "r"(a[3]), "r"(b[0]), "r"(b[1]));
}
__device__ __forceinline__ void mma_bf16(float* c, const unsigned* a, const unsigned* b) {
    asm volatile(
        "mma.sync.aligned.m16n8k16.row.col.f32.bf16.bf16.f32 "
        "{%0,%1,%2,%3}, {%4,%5,%6,%7}, {%8,%9}, {%0,%1,%2,%3};"
        : "+f"(c[0]), "+f"(c[1]), "+f"(c[2]), "+f"(c[3])
        : "r"(a[0]), "r"(a[1]), "r"(a[2]), "r"(a[3]), "r"(b[0]), "r"(b[1]));
}
__device__ __forceinline__ void ldsm4(unsigned* r, uint32_t a) {
    asm volatile("ldmatrix.sync.aligned.m8n8.x4.shared.b16 {%0,%1,%2,%3}, [%4];"
        : "=r"(r[0]), "=r"(r[1]), "=r"(r[2]), "=r"(r[3]) : "r"(a));
}
__device__ __forceinline__ uint32_t smem_u32(const void* p) {
    uint32_t a;
    asm("{ .reg .u64 t; cvta.to.shared.u64 t, %1; cvt.u32.u64 %0, t; }" : "=r"(a) : "l"(p));
    return a;
}
__device__ __forceinline__ void cp16(uint32_t s, const void* g) {
    asm volatile("cp.async.cg.shared.global [%0], [%1], 16;" :: "r"(s), "l"(g));
}
#define CP_COMMIT() asm volatile("cp.async.commit_group;")
#define CP_WAIT1()  asm volatile("cp.async.wait_group 1;")
#define CP_WAIT0()  asm volatile("cp.async.wait_group 0;")

// bf16 split: hi = bf16_rn(x), lo = bf16_rn(x - hi); pack pairs (low half = first)
__device__ __forceinline__ void split2(float a, float b, unsigned& hi, unsigned& lo) {
    unsigned short ha, hb, la, lb;
    asm("cvt.rn.bf16.f32 %0, %1;" : "=h"(ha) : "f"(a));
    asm("cvt.rn.bf16.f32 %0, %1;" : "=h"(hb) : "f"(b));
    float ra = a - __uint_as_float((unsigned)ha << 16);
    float rb = b - __uint_as_float((unsigned)hb << 16);
    asm("cvt.rn.bf16.f32 %0, %1;" : "=h"(la) : "f"(ra));
    asm("cvt.rn.bf16.f32 %0, %1;" : "=h"(lb) : "f"(rb));
    hi = (unsigned)ha | ((unsigned)hb << 16);
    lo = (unsigned)la | ((unsigned)lb << 16);
}

// Tile config (tf32 kernels): CTA 128x128x32, 4 warps (2x2, 64x64 warp tiles).
#define MT  128
#define NT  128
#define BK  32
#define STAGES 3
#define NTHREADS 128
#define AS_STRIDE 36
#define BS_STRIDE 136
#define A_BYTES  (128 * AS_STRIDE * 4)
#define B_BYTES  (128 * AS_STRIDE * 4)
#define STAGE_BYTES (A_BYTES + B_BYTES)
#define SMEM_DYN (STAGES * STAGE_BYTES)

// ---------------------------------------------------------------------------
// tf32 template (unchanged from R14)
// ---------------------------------------------------------------------------
template <bool TB, bool EXPE, bool NORM, bool CVA, bool CVB, bool ROUND, bool QKV3>
__global__ void __launch_bounds__(NTHREADS, 2) gemm_mha(
    const float* __restrict__ A, const float* __restrict__ B0,
    const float* __restrict__ B1, const float* __restrict__ B2,
    float* __restrict__ C, float* __restrict__ Aw, float* __restrict__ rs,
    int K, int lda, int ldb, int ldc,
    long long sA, long long sB, long long sC, float alpha, int S)
{
    extern __shared__ char smem[];
    const uint32_t sbase = smem_u32(smem);
    const int tid = threadIdx.x;
    const int lane = tid & 31;
    const int warp = tid >> 5;
    const int lg = lane >> 2;
    const int l4 = lane & 3;
    const int wm = (warp & 1) * 64;
    const int wn = (warp >> 1) * 64;

    const int lgp = lane >> 3, ri = lane & 7;
    const uint32_t aoff = (uint32_t)((wm + ((lgp & 1) << 3) + ri) * (AS_STRIDE * 4)
                                     + ((lgp >> 1) << 4));
    const uint32_t boff = (uint32_t)((wn + ((lgp >> 1) << 3) + ri) * (AS_STRIDE * 4)
                                     + ((lgp & 1) << 4));

    const int m0 = blockIdx.y * MT;
    int n0;
    const float* B;
    float* Cm;
    bool trc = false;
    if (QKV3) {
        const int bsel = blockIdx.x >> 3;
        n0 = (blockIdx.x & 7) * NT;
        B = (bsel == 0) ? B0 : ((bsel == 1) ? B1 : B2);
        Cm = C + (long long)bsel * sC;
        trc = (bsel == 2);
        if (blockIdx.x == 0) {
            float4 z = make_float4(0.f, 0.f, 0.f, 0.f);
            float* p = rs + blockIdx.y * (NHEAD * S / 32) + tid * 8;
            *(float4*)p = z;
            *(float4*)(p + 4) = z;
        }
    } else {
        n0 = blockIdx.x * NT;
        B = B0;
        Cm = C + (long long)blockIdx.z * sC;
    }

    const float* Ab = A + (long long)blockIdx.z * sA + (long long)m0 * lda;
    float* Awb = NORM ? (Aw + (long long)blockIdx.z * sA + (long long)m0 * lda) : nullptr;
    const float* Bb;
    if (TB) Bb = B + (long long)blockIdx.z * sB + (long long)n0 * ldb;
    else    Bb = B + (long long)blockIdx.z * sB + n0;
    float* Cb = Cm + (long long)m0 * ldc + n0;

    const int a_r = tid >> 3;
    const int a_c = (tid & 7) * 4;
    const int bn_k = tid >> 5;
    const int bn_c = (tid & 31) * 4;

    float inv[8];
    if (NORM) {
#pragma unroll
        for (int i = 0; i < 8; i++)
            inv[i] = 1.0f / rs[blockIdx.z * S + m0 + a_r + 16 * i];
    }

    float acc[4][8][4];
#pragma unroll
    for (int mt = 0; mt < 4; mt++)
#pragma unroll
        for (int nt = 0; nt < 8; nt++)
#pragma unroll
            for (int i = 0; i < 4; i++) acc[mt][nt][i] = 0.0f;

    const int ktiles = K / BK;

    auto issueA = [&](int st, int kt) {
        const uint32_t as = sbase + st * STAGE_BYTES;
        const float* p = Ab + (long long)a_r * lda + kt * BK + a_c;
#pragma unroll
        for (int i = 0; i < 8; i++)
            cp16(as + (uint32_t)(((a_r + 16 * i) * AS_STRIDE + a_c) * 4),
                 p + (long long)(16 * i) * lda);
    };
    auto issueB = [&](int st, int kt) {
        const uint32_t bs = sbase + st * STAGE_BYTES + A_BYTES;
        if (TB) {
            const float* p = Bb + (long long)a_r * ldb + kt * BK + a_c;
#pragma unroll
            for (int i = 0; i < 8; i++)
                cp16(bs + (uint32_t)(((a_r + 16 * i) * AS_STRIDE + a_c) * 4),
                     p + (long long)(16 * i) * ldb);
        } else {
            const float* p = Bb + (long long)(kt * BK + bn_k) * ldb + bn_c;
#pragma unroll
            for (int i = 0; i < 8; i++)
                cp16(bs + (uint32_t)(((bn_k + 4 * i) * BS_STRIDE + bn_c) * 4),
                     p + (long long)(4 * i) * ldb);
        }
    };
    auto wrNorm = [&](int st, int kt) {
        const float* As = (const float*)(smem + st * STAGE_BYTES);
#pragma unroll
        for (int i = 0; i < 8; i++) {
            float4 v = *(const float4*)&As[(a_r + 16 * i) * AS_STRIDE + a_c];
            v.x *= inv[i]; v.y *= inv[i]; v.z *= inv[i]; v.w *= inv[i];
            *(float4*)(Awb + (long long)(a_r + 16 * i) * lda + kt * BK + a_c) = v;
        }
    };

#pragma unroll
    for (int s = 0; s < 2; s++) {
        issueA(s, s);
        issueB(s, s);
        CP_COMMIT();
    }

    for (int kt = 0; kt < ktiles; kt++) {
        const int cur = kt % STAGES;
        const bool has = (kt + 2 < ktiles);
        if (has) CP_WAIT1(); else CP_WAIT0();
        __syncthreads();

        const int nx = (kt + 2) % STAGES;
        if (has) {
            issueA(nx, kt + 2);
            issueB(nx, kt + 2);
            CP_COMMIT();
        }

        if (NORM) wrNorm(cur, kt);

        const uint32_t as_s = sbase + cur * STAGE_BYTES;
        const uint32_t bs_s = as_s + A_BYTES;
        const float* Bs = (const float*)(smem + cur * STAGE_BYTES + A_BYTES);

#pragma unroll
        for (int ks = 0; ks < 4; ks++) {
            unsigned af[4][4], bf[8][2];
#pragma unroll
            for (int mt = 0; mt < 4; mt++) {
                unsigned r[4];
                ldsm4(r, as_s + aoff + (uint32_t)(mt * 16 * AS_STRIDE * 4 + ks * 32));
                af[mt][0] = CVA ? tf32u(r[0]) : r[0];
                af[mt][1] = CVA ? tf32u(r[1]) : r[1];
                af[mt][2] = CVA ? tf32u(r[2]) : r[2];
                af[mt][3] = CVA ? tf32u(r[3]) : r[3];
            }
            if (TB) {
#pragma unroll
                for (int np = 0; np < 4; np++) {
                    unsigned r[4];
                    ldsm4(r, bs_s + boff + (uint32_t)(np * 16 * AS_STRIDE * 4 + ks * 32));
                    bf[2 * np][0]     = CVB ? tf32u(r[0]) : r[0];
                    bf[2 * np][1]     = CVB ? tf32u(r[1]) : r[1];
                    bf[2 * np + 1][0] = CVB ? tf32u(r[2]) : r[2];
                    bf[2 * np + 1][1] = CVB ? tf32u(r[3]) : r[3];
                }
            } else {
                const int k = ks * 8;
#pragma unroll
                for (int nt = 0; nt < 8; nt++) {
                    const int c = wn + nt * 8 + lg;
                    unsigned v0 = __float_as_uint(Bs[(k + l4) * BS_STRIDE + c]);
                    unsigned v1 = __float_as_uint(Bs[(k + l4 + 4) * BS_STRIDE + c]);
                    bf[nt][0] = CVB ? tf32u(v0) : v0;
                    bf[nt][1] = CVB ? tf32u(v1) : v1;
                }
            }
#pragma unroll
            for (int mt = 0; mt < 4; mt++)
#pragma unroll
                for (int nt = 0; nt < 8; nt++)
                    mma_tf32(acc[mt][nt], af[mt], bf[nt]);
        }
    }

    if (EXPE) {
        float ps[4][2];
#pragma unroll
        for (int mt = 0; mt < 4; mt++) { ps[mt][0] = 0.0f; ps[mt][1] = 0.0f; }
#pragma unroll
        for (int mt = 0; mt < 4; mt++) {
            const int r = wm + mt * 16 + lg;
#pragma unroll
            for (int nt = 0; nt < 8; nt++) {
                const int c = wn + nt * 8 + 2 * l4;
                float e0 = __expf(acc[mt][nt][0] * alpha);
                float e1 = __expf(acc[mt][nt][1] * alpha);
                float e2 = __expf(acc[mt][nt][2] * alpha);
                float e3 = __expf(acc[mt][nt][3] * alpha);
                *(float2*)(Cb + (long long)r * ldc + c) = make_float2(e0, e1);
                *(float2*)(Cb + (long long)(r + 8) * ldc + c) = make_float2(e2, e3);
                ps[mt][0] += e0 + e1;
                ps[mt][1] += e2 + e3;
            }
        }
#pragma unroll
        for (int mt = 0; mt < 4; mt++) {
#pragma unroll
            for (int h = 0; h < 2; h++) {
                float v = ps[mt][h];
                v += __shfl_xor_sync(0xffffffffu, v, 1);
                v += __shfl_xor_sync(0xffffffffu, v, 2);
                if (l4 == 0)
                    atomicAdd(&rs[blockIdx.z * S + m0 + wm + mt * 16 + lg + h * 8], v);
            }
        }
    } else {
#pragma unroll
        for (int mt = 0; mt < 4; mt++) {
            const int r = wm + mt * 16 + lg;
            float s0 = alpha, s1 = alpha;
            if (NORM) {
                s0 = 1.0f / rs[blockIdx.z * S + m0 + r];
                s1 = 1.0f / rs[blockIdx.z * S + m0 + r + 8];
            }
#pragma unroll
            for (int nt = 0; nt < 8; nt++) {
                const int c = wn + nt * 8 + 2 * l4;
                float o0 = acc[mt][nt][0] * s0, o1 = acc[mt][nt][1] * s0;
                float o2 = acc[mt][nt][2] * s1, o3 = acc[mt][nt][3] * s1;
                if (ROUND) {
                    o0 = tf32f(o0); o1 = tf32f(o1);
                    o2 = tf32f(o2); o3 = tf32f(o3);
                }
                if (QKV3 && trc) {
                    const long long gm = m0 + r;
                    const int gc = n0 + c;
                    Aw[(long long)gc * S + gm]           = o0;
                    Aw[(long long)(gc + 1) * S + gm]     = o1;
                    Aw[(long long)gc * S + gm + 8]       = o2;
                    Aw[(long long)(gc + 1) * S + gm + 8] = o3;
                } else {
                    *(float2*)(Cb + (long long)r * ldc + c) = make_float2(o0, o1);
                    *(float2*)(Cb + (long long)(r + 8) * ldc + c) = make_float2(o2, o3);
                }
            }
        }
    }
}

// ---------------------------------------------------------------------------
// PROJ probe: C[M,N] = A[M,K] @ B[K,N] via bf16x2 3-term split (m16n8k16).
// CTA 128x128x32, 4 warps (64x64 tiles), double-buffered smem, 2 CTAs/SM.
// smem planes per stage: AH/AL bf16 [128][40], BH/BL u32-packed [16][136].
// ---------------------------------------------------------------------------
#define PB_AH 0
#define PB_AL 10240
#define PB_BH 20480
#define PB_BL 29184
#define PB_STAGE 37888
#define PB_SMEM (2 * PB_STAGE)

__global__ void __launch_bounds__(128, 2) proj_bf16x2(
    const float* __restrict__ A, const float* __restrict__ B, float* __restrict__ C,
    int K, int lda, int ldb, int ldc)
{
    extern __shared__ char smem[];
    const uint32_t sbase = smem_u32(smem);
    const int tid = threadIdx.x;
    const int lane = tid & 31;
    const int warp = tid >> 5;
    const int lg = lane >> 2;
    const int l4 = lane & 3;
    const int wm = (warp & 1) * 64;
    const int wn = (warp >> 1) * 64;
    const int lgp = lane >> 3, ri = lane & 7;
    // A-plane ldmatrix lane offset: rows stride 80B, 16B k-groups
    const uint32_t aoffb = (uint32_t)((wm + ((lgp & 1) << 3) + ri) * 80 + ((lgp >> 1) << 4));

    const int m0 = blockIdx.y * 128;
    const int n0 = blockIdx.x * 128;
    const float* Ab = A + (long long)m0 * lda;
    const float* Bb = B + n0;
    float* Cb = C + (long long)m0 * ldc + n0;

    const int a_r = tid >> 3;            // 0..15 (+16i)
    const int a_c = (tid & 7) * 4;
    const int pb = tid >> 5;             // 0..3 (+4i -> pair idx 0..15)
    const int bn_c = (tid & 31) * 4;

    float acc[4][8][4];
#pragma unroll
    for (int mt = 0; mt < 4; mt++)
#pragma unroll
        for (int nt = 0; nt < 8; nt++)
#pragma unroll
            for (int i = 0; i < 4; i++) acc[mt][nt][i] = 0.0f;

    const int ktiles = K / 32;
    float4 pa[8], pbv[8];

    auto ldA = [&](int kt) {
        const float* p = Ab + (long long)a_r * lda + kt * 32 + a_c;
#pragma unroll
        for (int i = 0; i < 8; i++)
            pa[i] = *(const float4*)(p + (long long)(16 * i) * lda);
    };
    auto ldB = [&](int kt) {
#pragma unroll
        for (int i = 0; i < 4; i++) {
            const int p2 = pb + 4 * i;
            pbv[2 * i]     = *(const float4*)(Bb + (long long)(kt * 32 + 2 * p2) * ldb + bn_c);
            pbv[2 * i + 1] = *(const float4*)(Bb + (long long)(kt * 32 + 2 * p2 + 1) * ldb + bn_c);
        }
    };
    auto stA = [&](int st) {
        char* ah = smem + st * PB_STAGE + PB_AH;
        char* al = smem + st * PB_STAGE + PB_AL;
#pragma unroll
        for (int i = 0; i < 8; i++) {
            unsigned h0, l0, h1, l1;
            split2(pa[i].x, pa[i].y, h0, l0);
            split2(pa[i].z, pa[i].w, h1, l1);
            const int off = (a_r + 16 * i) * 80 + a_c * 2;
            *(uint2*)(ah + off) = make_uint2(h0, h1);
            *(uint2*)(al + off) = make_uint2(l0, l1);
        }
    };
    auto stB = [&](int st) {
        unsigned* bh = (unsigned*)(smem + st * PB_STAGE + PB_BH);
        unsigned* bl = (unsigned*)(smem + st * PB_STAGE + PB_BL);
#pragma unroll
        for (int i = 0; i < 4; i++) {
            const int p2 = pb + 4 * i;
            uint4 vh, vl;
            unsigned h, l, h2, l2;
            split2(pbv[2 * i].x, 0.f, h, l); split2(pbv[2 * i + 1].x, 0.f, h2, l2);
            vh.x = (h & 0xFFFF) | (h2 << 16); vl.x = (l & 0xFFFF) | (l2 << 16);
            split2(pbv[2 * i].y, 0.f, h, l); split2(pbv[2 * i + 1].y, 0.f, h2, l2);
            vh.y = (h & 0xFFFF) | (h2 << 16); vl.y = (l & 0xFFFF) | (l2 << 16);
            split2(pbv[2 * i].z, 0.f, h, l); split2(pbv[2 * i + 1].z, 0.f, h2, l2);
            vh.z = (h & 0xFFFF) | (h2 << 16); vl.z = (l & 0xFFFF) | (l2 << 16);
            split2(pbv[2 * i].w, 0.f, h, l); split2(pbv[2 * i + 1].w, 0.f, h2, l2);
            vh.w = (h & 0xFFFF) | (h2 << 16); vl.w = (l & 0xFFFF) | (l2 << 16);
            *(uint4*)&bh[p2 * 136 + bn_c] = vh;
            *(uint4*)&bl[p2 * 136 + bn_c] = vl;
        }
    };

    // prologue
    ldA(0); ldB(0); stA(0); stB(0);
    __syncthreads();

    for (int kt = 0; kt < ktiles; kt++) {
        const int cur = kt & 1;
        const bool has = (kt + 1 < ktiles);
        if (has) { ldA(kt + 1); ldB(kt + 1); }

        const uint32_t ah_s = sbase + cur * PB_STAGE + PB_AH;
        const uint32_t al_s = sbase + cur * PB_STAGE + PB_AL;
        const unsigned* BH = (const unsigned*)(smem + cur * PB_STAGE + PB_BH);
        const unsigned* BL = (const unsigned*)(smem + cur * PB_STAGE + PB_BL);

#pragma unroll
        for (int ks = 0; ks < 2; ks++) {   // two k16 steps per kt (BK=32)
            unsigned af[4][4], bfr[8][2];
            // term 1: Ah * Bh
#pragma unroll
            for (int mt = 0; mt < 4; mt++)
                ldsm4(af[mt], ah_s + aoffb + (uint32_t)(mt * 16 * 80 + ks * 32));
#pragma unroll
            for (int nt = 0; nt < 8; nt++) {
                bfr[nt][0] = BH[(ks * 8 + l4) * 136 + wn + nt * 8 + lg];
                bfr[nt][1] = BH[(ks * 8 + l4 + 4) * 136 + wn + nt * 8 + lg];
            }
#pragma unroll
            for (int mt = 0; mt < 4; mt++)
#pragma unroll
                for (int nt = 0; nt < 8; nt++)
                    mma_bf16(acc[mt][nt], af[mt], bfr[nt]);
            // term 2: Ah * Bl
#pragma unroll
            for (int nt = 0; nt < 8; nt++) {
                bfr[nt][0] = BL[(ks * 8 + l4) * 136 + wn + nt * 8 + lg];
                bfr[nt][1] = BL[(ks * 8 + l4 + 4) * 136 + wn + nt * 8 + lg];
            }
#pragma unroll
            for (int mt = 0; mt < 4; mt++)
#pragma unroll
                for (int nt = 0; nt < 8; nt++)
                    mma_bf16(acc[mt][nt], af[mt], bfr[nt]);
            // term 3: Al * Bh
#pragma unroll
            for (int mt = 0; mt < 4; mt++)
                ldsm4(af[mt], al_s + aoffb + (uint32_t)(mt * 16 * 80 + ks * 32));
#pragma unroll
            for (int nt = 0; nt < 8; nt++) {
                bfr[nt][0] = BH[(ks * 8 + l4) * 136 + wn + nt * 8 + lg];
                bfr[nt][1] = BH[(ks * 8 + l4 + 4) * 136 + wn + nt * 8 + lg];
            }
#pragma unroll
            for (int mt = 0; mt < 4; mt++)
#pragma unroll
                for (int nt = 0; nt < 8; nt++)
                    mma_bf16(acc[mt][nt], af[mt], bfr[nt]);
        }

        __syncthreads();
        if (has) {
            stA(cur ^ 1);
            stB(cur ^ 1);
            __syncthreads();
        }
    }

    // epilogue (same C fragment mapping as m16n8k8)
#pragma unroll
    for (int mt = 0; mt < 4; mt++) {
        const int r = wm + mt * 16 + lg;
#pragma unroll
        for (int nt = 0; nt < 8; nt++) {
            const int c = wn + nt * 8 + 2 * l4;
            *(float2*)(Cb + (long long)r * ldc + c) =
                make_float2(acc[mt][nt][0], acc[mt][nt][1]);
            *(float2*)(Cb + (long long)(r + 8) * ldc + c) =
                make_float2(acc[mt][nt][2], acc[mt][nt][3]);
        }
    }
}

extern "C" void kernel_launch(void* const* d_in, const int* in_sizes, int n_in,
                              void* d_out, int out_size)
{
    const float* x  = (const float*)d_in[0];
    const float* Wq = (const float*)d_in[1];
    const float* Wk = (const float*)d_in[2];
    const float* Wv = (const float*)d_in[3];
    const float* Wo = (const float*)d_in[4];

    const int F  = 1024;
    const int H  = 1024;
    const int NH = NHEAD;
    const int DK = H / NH;
    const int S  = in_sizes[0] / F;

    float* y_out    = (float*)d_out;
    float* attn_out = y_out + (long long)S * H;

    float *qkv, *vt, *y, *rs;
    cudaGetSymbolAddress((void**)&qkv, g_qkv);
    cudaGetSymbolAddress((void**)&vt, g_vt);
    cudaGetSymbolAddress((void**)&y, g_y);
    cudaGetSymbolAddress((void**)&rs, g_rs);
    float* q = qkv;
    float* k = qkv + (long long)S * H;

    auto kQKV  = gemm_mha<false, false, false, true,  true,  true,  true >;
    auto kQKT  = gemm_mha<true,  true,  false, false, false, false, false>;
    auto kAV   = gemm_mha<true,  false, true,  true,  false, true,  false>;

    cudaFuncSetAttribute(kQKV,  cudaFuncAttributeMaxDynamicSharedMemorySize, SMEM_DYN);
    cudaFuncSetAttribute(kQKT,  cudaFuncAttributeMaxDynamicSharedMemorySize, SMEM_DYN);
    cudaFuncSetAttribute(kAV,   cudaFuncAttributeMaxDynamicSharedMemorySize, SMEM_DYN);
    cudaFuncSetAttribute(proj_bf16x2,
                         cudaFuncAttributeMaxDynamicSharedMemorySize, PB_SMEM);

    const dim3 blk(NTHREADS);
    const float inv_sqrt_dk = 0.08838834764831845f;

    // 1) fused Q/K/V projections (+rs zeroing); v written transposed to g_vt
    dim3 g1(3 * (H / NT), S / MT, 1);
    kQKV<<<g1, blk, SMEM_DYN>>>(x, Wq, Wk, Wv, qkv, vt, rs,
                                F, F, H, H, 0, 0, (long long)S * H, 1.0f, S);

    // 2) logits -> exp(Q K^T / sqrt(dk)) fp32 into attn region + raw row sums
    dim3 g2(S / NT, S / MT, NH);
    kQKT<<<g2, blk, SMEM_DYN>>>(q, k, nullptr, nullptr, attn_out, nullptr, rs,
                                DK, H, H, S,
                                (long long)DK, (long long)DK, (long long)S * S,
                                inv_sqrt_dk, S);

    // 3) AV (TB, all-ldsm): Y = (E @ Vt^T)/rs; writes normalized attn from smem
    dim3 g3(DK / NT, S / MT, NH);
    kAV<<<g3, blk, SMEM_DYN>>>(attn_out, vt, nullptr, nullptr, y, attn_out, rs,
                               S, S, S, H,
                               (long long)S * S, (long long)DK * S, (long long)DK,
                               1.0f, S);

    // 4) output projection (bf16x2 split probe): y_out = Y @ Wo
    dim3 g4(F / 128, S / 128, 1);
    proj_bf16x2<<<g4, blk, PB_SMEM>>>(y, Wo, y_out, H, H, F, F);
}

// round 16
// speedup vs baseline: 1.2069x; 1.2069x over previous
#include <cuda_runtime.h>
#include <cuda_fp16.h>
#include <cstdint>
#include <math.h>

// ---------------------------------------------------------------------------
// MultiHeadAttention. QKV/PROJ: tf32 mma path (R14 config, QKV emits fp16).
// QKT/AV: fp16 m16n8k16 path (2x K per mma at same instruction cost).
// d_out = y [S,F] then attn [8,S,S] (fp32). S=4096, F=H=1024, dk=128.
// ---------------------------------------------------------------------------

#define SMAX 4096
#define HMAX 1024
#define NHEAD 8

__device__ __half g_qk[2 * SMAX * HMAX];                 // q | k fp16 [S][H]
__device__ __half g_vt[HMAX * SMAX];                     // v^T fp16 [H][S]
__device__ __half g_eh[(size_t)NHEAD * SMAX * SMAX];     // raw exp fp16
__device__ float  g_y[SMAX * HMAX];                      // Y fp32
__device__ float  g_rs[NHEAD * SMAX];                    // raw row sums

__device__ __forceinline__ unsigned tf32u(unsigned x) {
    unsigned r;
    asm("cvt.rna.tf32.f32 %0, %1;" : "=r"(r) : "f"(__uint_as_float(x)));
    return r;
}
__device__ __forceinline__ float tf32f(float x) {
    unsigned r;
    asm("cvt.rna.tf32.f32 %0, %1;" : "=r"(r) : "f"(x));
    return __uint_as_float(r);
}
__device__ __forceinline__ void mma_tf32(float* c, const unsigned* a, const unsigned* b) {
    asm volatile(
        "mma.sync.aligned.m16n8k8.row.col.f32.tf32.tf32.f32 "
        "{%0,%1,%2,%3}, {%4,%5,%6,%7}, {%8,%9}, {%0,%1,%2,%3};"
        : "+f"(c[0]), "+f"(c[1]), "+f"(c[2]), "+f"(c[3])
        : "r"(a[0]), "r"(a[1]), "r"(a[2]), "r"(a[3]), "r"(b[0]), "r"(b[1]));
}
__device__ __forceinline__ void mma_f16(float* c, const unsigned* a, const unsigned* b) {
    asm volatile(
        "mma.sync.aligned.m16n8k16.row.col.f32.f16.f16.f32 "
        "{%0,%1,%2,%3}, {%4,%5,%6,%7}, {%8,%9}, {%0,%1,%2,%3};"
        : "+f"(c[0]), "+f"(c[1]), "+f"(c[2]), "+f"(c[3])
        : "r"(a[0]), "r"(a[1]), "r"(a[2]), "r"(a[3]), "r"(b[0]), "r"(b[1]));
}
__device__ __forceinline__ void ldsm4(unsigned* r, uint32_t a) {
    asm volatile("ldmatrix.sync.aligned.m8n8.x4.shared.b16 {%0,%1,%2,%3}, [%4];"
        : "=r"(r[0]), "=r"(r[1]), "=r"(r[2]), "=r"(r[3]) : "r"(a));
}
__device__ __forceinline__ uint32_t smem_u32(const void* p) {
    uint32_t a;
    asm("{ .reg .u64 t; cvta.to.shared.u64 t, %1; cvt.u32.u64 %0, t; }" : "=r"(a) : "l"(p));
    return a;
}
__device__ __forceinline__ void cp16(uint32_t s, const void* g) {
    asm volatile("cp.async.cg.shared.global [%0], [%1], 16;" :: "r"(s), "l"(g));
}
#define CP_COMMIT() asm volatile("cp.async.commit_group;")
#define CP_WAIT1()  asm volatile("cp.async.wait_group 1;")
#define CP_WAIT0()  asm volatile("cp.async.wait_group 0;")

// ---------------- tf32 kernel (QKV fused + PROJ) ---------------------------
#define MT  128
#define NT  128
#define BK  32
#define STAGES 3
#define NTHREADS 128
#define AS_STRIDE 36
#define BS_STRIDE 136
#define A_BYTES  (128 * AS_STRIDE * 4)
#define B_BYTES  (128 * AS_STRIDE * 4)
#define STAGE_BYTES (A_BYTES + B_BYTES)
#define SMEM_DYN (STAGES * STAGE_BYTES)

// QKV3: blockIdx.x = (bsel<<3)|ntile; bsel 0/1 -> fp16 q/k into H16A (+bsel*sC),
// bsel 2 -> fp16 transposed into VT16 [H][S]. blockIdx.x==0 CTAs zero rs.
template <bool TB, bool CVA, bool CVB, bool ROUND, bool QKV3>
__global__ void __launch_bounds__(NTHREADS, 2) gemm_tf32k(
    const float* __restrict__ A, const float* __restrict__ B0,
    const float* __restrict__ B1, const float* __restrict__ B2,
    float* __restrict__ C, __half* __restrict__ H16A, __half* __restrict__ VT16,
    float* __restrict__ rs,
    int K, int lda, int ldb, int ldc,
    long long sC, float alpha, int S)
{
    extern __shared__ char smem[];
    const uint32_t sbase = smem_u32(smem);
    const int tid = threadIdx.x;
    const int lane = tid & 31;
    const int warp = tid >> 5;
    const int lg = lane >> 2;
    const int l4 = lane & 3;
    const int wm = (warp & 1) * 64;
    const int wn = (warp >> 1) * 64;
    const int lgp = lane >> 3, ri = lane & 7;
    const uint32_t aoff = (uint32_t)((wm + ((lgp & 1) << 3) + ri) * (AS_STRIDE * 4)
                                     + ((lgp >> 1) << 4));
    const uint32_t boff = (uint32_t)((wn + ((lgp >> 1) << 3) + ri) * (AS_STRIDE * 4)
                                     + ((lgp & 1) << 4));

    const int m0 = blockIdx.y * MT;
    int n0, bsel = 0;
    const float* B;
    if (QKV3) {
        bsel = blockIdx.x >> 3;
        n0 = (blockIdx.x & 7) * NT;
        B = (bsel == 0) ? B0 : ((bsel == 1) ? B1 : B2);
        if (blockIdx.x == 0) {
            float4 z = make_float4(0.f, 0.f, 0.f, 0.f);
            float* p = rs + blockIdx.y * (NHEAD * S / 32) + tid * 8;
            *(float4*)p = z;
            *(float4*)(p + 4) = z;
        }
    } else {
        n0 = blockIdx.x * NT;
        B = B0;
    }

    const float* Ab = A + (long long)m0 * lda;
    const float* Bb;
    if (TB) Bb = B + (long long)n0 * ldb;
    else    Bb = B + n0;
    float* Cb = C + (long long)m0 * ldc + n0;
    __half* Cb16 = QKV3 ? (H16A + (long long)bsel * sC + (long long)m0 * ldc + n0) : nullptr;

    const int a_r = tid >> 3;
    const int a_c = (tid & 7) * 4;
    const int bn_k = tid >> 5;
    const int bn_c = (tid & 31) * 4;

    float acc[4][8][4];
#pragma unroll
    for (int mt = 0; mt < 4; mt++)
#pragma unroll
        for (int nt = 0; nt < 8; nt++)
#pragma unroll
            for (int i = 0; i < 4; i++) acc[mt][nt][i] = 0.0f;

    const int ktiles = K / BK;

    auto issueA = [&](int st, int kt) {
        const uint32_t as = sbase + st * STAGE_BYTES;
        const float* p = Ab + (long long)a_r * lda + kt * BK + a_c;
#pragma unroll
        for (int i = 0; i < 8; i++)
            cp16(as + (uint32_t)(((a_r + 16 * i) * AS_STRIDE + a_c) * 4),
                 p + (long long)(16 * i) * lda);
    };
    auto issueB = [&](int st, int kt) {
        const uint32_t bs = sbase + st * STAGE_BYTES + A_BYTES;
        if (TB) {
            const float* p = Bb + (long long)a_r * ldb + kt * BK + a_c;
#pragma unroll
            for (int i = 0; i < 8; i++)
                cp16(bs + (uint32_t)(((a_r + 16 * i) * AS_STRIDE + a_c) * 4),
                     p + (long long)(16 * i) * ldb);
        } else {
            const float* p = Bb + (long long)(kt * BK + bn_k) * ldb + bn_c;
#pragma unroll
            for (int i = 0; i < 8; i++)
                cp16(bs + (uint32_t)(((bn_k + 4 * i) * BS_STRIDE + bn_c) * 4),
                     p + (long long)(4 * i) * ldb);
        }
    };

#pragma unroll
    for (int s = 0; s < 2; s++) {
        issueA(s, s);
        issueB(s, s);
        CP_COMMIT();
    }

    for (int kt = 0; kt < ktiles; kt++) {
        const int cur = kt % STAGES;
        const bool has = (kt + 2 < ktiles);
        if (has) CP_WAIT1(); else CP_WAIT0();
        __syncthreads();

        const int nx = (kt + 2) % STAGES;
        if (has) {
            issueA(nx, kt + 2);
            issueB(nx, kt + 2);
            CP_COMMIT();
        }

        const uint32_t as_s = sbase + cur * STAGE_BYTES;
        const uint32_t bs_s = as_s + A_BYTES;
        const float* Bs = (const float*)(smem + cur * STAGE_BYTES + A_BYTES);

#pragma unroll
        for (int ks = 0; ks < 4; ks++) {
            unsigned af[4][4], bf[8][2];
#pragma unroll
            for (int mt = 0; mt < 4; mt++) {
                unsigned r[4];
                ldsm4(r, as_s + aoff + (uint32_t)(mt * 16 * AS_STRIDE * 4 + ks * 32));
                af[mt][0] = CVA ? tf32u(r[0]) : r[0];
                af[mt][1] = CVA ? tf32u(r[1]) : r[1];
                af[mt][2] = CVA ? tf32u(r[2]) : r[2];
                af[mt][3] = CVA ? tf32u(r[3]) : r[3];
            }
            if (TB) {
#pragma unroll
                for (int np = 0; np < 4; np++) {
                    unsigned r[4];
                    ldsm4(r, bs_s + boff + (uint32_t)(np * 16 * AS_STRIDE * 4 + ks * 32));
                    bf[2 * np][0]     = CVB ? tf32u(r[0]) : r[0];
                    bf[2 * np][1]     = CVB ? tf32u(r[1]) : r[1];
                    bf[2 * np + 1][0] = CVB ? tf32u(r[2]) : r[2];
                    bf[2 * np + 1][1] = CVB ? tf32u(r[3]) : r[3];
                }
            } else {
                const int k = ks * 8;
#pragma unroll
                for (int nt = 0; nt < 8; nt++) {
                    const int c = wn + nt * 8 + lg;
                    unsigned v0 = __float_as_uint(Bs[(k + l4) * BS_STRIDE + c]);
                    unsigned v1 = __float_as_uint(Bs[(k + l4 + 4) * BS_STRIDE + c]);
                    bf[nt][0] = CVB ? tf32u(v0) : v0;
                    bf[nt][1] = CVB ? tf32u(v1) : v1;
                }
            }
#pragma unroll
            for (int mt = 0; mt < 4; mt++)
#pragma unroll
                for (int nt = 0; nt < 8; nt++)
                    mma_tf32(acc[mt][nt], af[mt], bf[nt]);
        }
    }

    // epilogue
#pragma unroll
    for (int mt = 0; mt < 4; mt++) {
        const int r = wm + mt * 16 + lg;
#pragma unroll
        for (int nt = 0; nt < 8; nt++) {
            const int c = wn + nt * 8 + 2 * l4;
            float o0 = acc[mt][nt][0] * alpha, o1 = acc[mt][nt][1] * alpha;
            float o2 = acc[mt][nt][2] * alpha, o3 = acc[mt][nt][3] * alpha;
            if (QKV3) {
                if (bsel < 2) {
                    *(__half2*)(Cb16 + (long long)r * ldc + c) = __floats2half2_rn(o0, o1);
                    *(__half2*)(Cb16 + (long long)(r + 8) * ldc + c) = __floats2half2_rn(o2, o3);
                } else {
                    const long long gm = m0 + r;
                    const int gc = n0 + c;
                    VT16[(long long)gc * S + gm]           = __float2half_rn(o0);
                    VT16[(long long)(gc + 1) * S + gm]     = __float2half_rn(o1);
                    VT16[(long long)gc * S + gm + 8]       = __float2half_rn(o2);
                    VT16[(long long)(gc + 1) * S + gm + 8] = __float2half_rn(o3);
                }
            } else {
                if (ROUND) {
                    o0 = tf32f(o0); o1 = tf32f(o1);
                    o2 = tf32f(o2); o3 = tf32f(o3);
                }
                *(float2*)(Cb + (long long)r * ldc + c) = make_float2(o0, o1);
                *(float2*)(Cb + (long long)(r + 8) * ldc + c) = make_float2(o2, o3);
            }
        }
    }
}

// ---------------- fp16 kernel (QKT + AV) -----------------------------------
// Both operands fp16, TB layout ([rows][k] K-major). CTA 128x128x32, 4 warps,
// warp tile 64x64, m16n8k16 mma, cp.async 3-stage, 2 CTAs/SM.
// EXPE: C = fp16(exp(alpha*acc)) to Ce + rowsum atomicAdd to rs.
// NORM: A tiles are raw E; after landing, tile re-read from smem, scaled by
//       1/rs, written as fp32 attn to Aw; epilogue Cf = tf32(acc/rs).
#define HSB 80                      // fp16 tile row stride (bytes), 40 halves
#define H_TILE (128 * HSB)          // 10240
#define H_STAGE (2 * H_TILE)        // 20480
#define H_SMEM (STAGES * H_STAGE)   // 61440

template <bool EXPE, bool NORM>
__global__ void __launch_bounds__(128, 2) gemm_h16(
    const __half* __restrict__ A, const __half* __restrict__ B,
    __half* __restrict__ Ce, float* __restrict__ Cf,
    float* __restrict__ Aw, float* __restrict__ rs,
    int K, int lda, int ldb, int ldc,
    long long sA, long long sB, long long sC, float alpha, int S)
{
    extern __shared__ char smem[];
    const uint32_t sbase = smem_u32(smem);
    const int tid = threadIdx.x;
    const int lane = tid & 31;
    const int warp = tid >> 5;
    const int lg = lane >> 2;
    const int l4 = lane & 3;
    const int wm = (warp & 1) * 64;
    const int wn = (warp >> 1) * 64;
    const int lgp = lane >> 3, ri = lane & 7;
    const uint32_t aoffh = (uint32_t)((wm + ((lgp & 1) << 3) + ri) * HSB + ((lgp >> 1) << 4));
    const uint32_t boffh = (uint32_t)((wn + ((lgp & 1) << 3) + ri) * HSB + ((lgp >> 1) << 4));

    const int m0 = blockIdx.y * 128;
    const int n0 = blockIdx.x * 128;
    const int z = blockIdx.z;

    const __half* Ab = A + (long long)z * sA + (long long)m0 * lda;
    const __half* Bb = B + (long long)z * sB + (long long)n0 * ldb;
    __half* Cbe = EXPE ? (Ce + (long long)z * sC + (long long)m0 * ldc + n0) : nullptr;
    float* Cbf = EXPE ? nullptr : (Cf + (long long)z * sC + (long long)m0 * ldc + n0);
    float* Awb = NORM ? (Aw + (long long)z * (long long)S * S + (long long)m0 * lda) : nullptr;

    const int row2 = tid >> 2;          // 0..31 (+32i)
    const int chk  = tid & 3;           // 16B chunk within 64B row

    float inv[4];
    if (NORM) {
#pragma unroll
        for (int i = 0; i < 4; i++)
            inv[i] = 1.0f / rs[z * S + m0 + row2 + 32 * i];
    }

    float acc[4][8][4];
#pragma unroll
    for (int mt = 0; mt < 4; mt++)
#pragma unroll
        for (int nt = 0; nt < 8; nt++)
#pragma unroll
            for (int i = 0; i < 4; i++) acc[mt][nt][i] = 0.0f;

    const int ktiles = K / 32;

    auto issueA = [&](int st, int kt) {
        const uint32_t as = sbase + st * H_STAGE;
        const __half* p = Ab + (long long)row2 * lda + kt * 32 + chk * 8;
#pragma unroll
        for (int i = 0; i < 4; i++)
            cp16(as + (uint32_t)((row2 + 32 * i) * HSB + chk * 16),
                 p + (long long)(32 * i) * lda);
    };
    auto issueB = [&](int st, int kt) {
        const uint32_t bs = sbase + st * H_STAGE + H_TILE;
        const __half* p = Bb + (long long)row2 * ldb + kt * 32 + chk * 8;
#pragma unroll
        for (int i = 0; i < 4; i++)
            cp16(bs + (uint32_t)((row2 + 32 * i) * HSB + chk * 16),
                 p + (long long)(32 * i) * ldb);
    };
    auto wrNorm = [&](int st, int kt) {
        const char* As = smem + st * H_STAGE;
#pragma unroll
        for (int i = 0; i < 4; i++) {
            const int row = row2 + 32 * i;
            const __half2* h = (const __half2*)(As + row * HSB + chk * 16);
            float* d = Awb + (long long)row * lda + kt * 32 + chk * 8;
            float4 v0, v1;
            float2 t;
            t = __half22float2(h[0]); v0.x = t.x * inv[i]; v0.y = t.y * inv[i];
            t = __half22float2(h[1]); v0.z = t.x * inv[i]; v0.w = t.y * inv[i];
            t = __half22float2(h[2]); v1.x = t.x * inv[i]; v1.y = t.y * inv[i];
            t = __half22float2(h[3]); v1.z = t.x * inv[i]; v1.w = t.y * inv[i];
            *(float4*)d = v0;
            *(float4*)(d + 4) = v1;
        }
    };

#pragma unroll
    for (int s = 0; s < 2; s++) {
        issueA(s, s);
        issueB(s, s);
        CP_COMMIT();
    }

    for (int kt = 0; kt < ktiles; kt++) {
        const int cur = kt % STAGES;
        const bool has = (kt + 2 < ktiles);
        if (has) CP_WAIT1(); else CP_WAIT0();
        __syncthreads();

        const int nx = (kt + 2) % STAGES;
        if (has) {
            issueA(nx, kt + 2);
            issueB(nx, kt + 2);
            CP_COMMIT();
        }

        if (NORM) wrNorm(cur, kt);

        const uint32_t as_s = sbase + cur * H_STAGE;
        const uint32_t bs_s = as_s + H_TILE;

#pragma unroll
        for (int ks = 0; ks < 2; ks++) {   // two k16 steps per BK=32
            unsigned af[4][4], bf[8][2];
#pragma unroll
            for (int mt = 0; mt < 4; mt++)
                ldsm4(af[mt], as_s + aoffh + (uint32_t)(mt * 16 * HSB + ks * 32));
#pragma unroll
            for (int np = 0; np < 4; np++) {
                unsigned r[4];
                ldsm4(r, bs_s + boffh + (uint32_t)(np * 16 * HSB + ks * 32));
                bf[2 * np][0]     = r[0];
                bf[2 * np + 1][0] = r[1];
                bf[2 * np][1]     = r[2];
                bf[2 * np + 1][1] = r[3];
            }
#pragma unroll
            for (int mt = 0; mt < 4; mt++)
#pragma unroll
                for (int nt = 0; nt < 8; nt++)
                    mma_f16(acc[mt][nt], af[mt], bf[nt]);
        }
    }

    // ---- epilogue ----
    if (EXPE) {
        float ps[4][2];
#pragma unroll
        for (int mt = 0; mt < 4; mt++) { ps[mt][0] = 0.0f; ps[mt][1] = 0.0f; }
#pragma unroll
        for (int mt = 0; mt < 4; mt++) {
            const int r = wm + mt * 16 + lg;
#pragma unroll
            for (int nt = 0; nt < 8; nt++) {
                const int c = wn + nt * 8 + 2 * l4;
                __half2 h01 = __floats2half2_rn(__expf(acc[mt][nt][0] * alpha),
                                                __expf(acc[mt][nt][1] * alpha));
                __half2 h23 = __floats2half2_rn(__expf(acc[mt][nt][2] * alpha),
                                                __expf(acc[mt][nt][3] * alpha));
                *(__half2*)(Cbe + (long long)r * ldc + c) = h01;
                *(__half2*)(Cbe + (long long)(r + 8) * ldc + c) = h23;
                float2 f01 = __half22float2(h01);
                float2 f23 = __half22float2(h23);
                ps[mt][0] += f01.x + f01.y;
                ps[mt][1] += f23.x + f23.y;
            }
        }
#pragma unroll
        for (int mt = 0; mt < 4; mt++) {
#pragma unroll
            for (int h = 0; h < 2; h++) {
                float v = ps[mt][h];
                v += __shfl_xor_sync(0xffffffffu, v, 1);
                v += __shfl_xor_sync(0xffffffffu, v, 2);
                if (l4 == 0)
                    atomicAdd(&rs[z * S + m0 + wm + mt * 16 + lg + h * 8], v);
            }
        }
    } else {
#pragma unroll
        for (int mt = 0; mt < 4; mt++) {
            const int r = wm + mt * 16 + lg;
            const float s0 = NORM ? 1.0f / rs[z * S + m0 + r] : 1.0f;
            const float s1 = NORM ? 1.0f / rs[z * S + m0 + r + 8] : 1.0f;
#pragma unroll
            for (int nt = 0; nt < 8; nt++) {
                const int c = wn + nt * 8 + 2 * l4;
                float o0 = tf32f(acc[mt][nt][0] * s0), o1 = tf32f(acc[mt][nt][1] * s0);
                float o2 = tf32f(acc[mt][nt][2] * s1), o3 = tf32f(acc[mt][nt][3] * s1);
                *(float2*)(Cbf + (long long)r * ldc + c) = make_float2(o0, o1);
                *(float2*)(Cbf + (long long)(r + 8) * ldc + c) = make_float2(o2, o3);
            }
        }
    }
}

extern "C" void kernel_launch(void* const* d_in, const int* in_sizes, int n_in,
                              void* d_out, int out_size)
{
    const float* x  = (const float*)d_in[0];
    const float* Wq = (const float*)d_in[1];
    const float* Wk = (const float*)d_in[2];
    const float* Wv = (const float*)d_in[3];
    const float* Wo = (const float*)d_in[4];

    const int F  = 1024;
    const int H  = 1024;
    const int NH = NHEAD;
    const int DK = H / NH;
    const int S  = in_sizes[0] / F;

    float* y_out    = (float*)d_out;
    float* attn_out = y_out + (long long)S * H;

    __half *qk, *vt, *eh;
    float *y, *rs;
    cudaGetSymbolAddress((void**)&qk, g_qk);
    cudaGetSymbolAddress((void**)&vt, g_vt);
    cudaGetSymbolAddress((void**)&eh, g_eh);
    cudaGetSymbolAddress((void**)&y, g_y);
    cudaGetSymbolAddress((void**)&rs, g_rs);
    __half* q = qk;
    __half* k = qk + (long long)S * H;

    // tf32 template args: TB, CVA, CVB, ROUND, QKV3
    auto kQKV  = gemm_tf32k<false, true,  true,  false, true >;
    auto kPROJ = gemm_tf32k<false, false, true,  false, false>;
    auto kQKT  = gemm_h16<true,  false>;
    auto kAV   = gemm_h16<false, true >;

    cudaFuncSetAttribute(kQKV,  cudaFuncAttributeMaxDynamicSharedMemorySize, SMEM_DYN);
    cudaFuncSetAttribute(kPROJ, cudaFuncAttributeMaxDynamicSharedMemorySize, SMEM_DYN);
    cudaFuncSetAttribute(kQKT,  cudaFuncAttributeMaxDynamicSharedMemorySize, H_SMEM);
    cudaFuncSetAttribute(kAV,   cudaFuncAttributeMaxDynamicSharedMemorySize, H_SMEM);

    const dim3 blk(NTHREADS);
    const float inv_sqrt_dk = 0.08838834764831845f;  // 1/sqrt(128)

    // 1) fused Q/K/V projections (+rs zeroing), fp16 outputs (q,k rows; v^T)
    dim3 g1(3 * (H / NT), S / MT, 1);
    kQKV<<<g1, blk, SMEM_DYN>>>(x, Wq, Wk, Wv, y /*unused*/, qk, vt, rs,
                                F, F, H, H, (long long)S * H, 1.0f, S);

    // 2) QKT (fp16): E = fp16(exp(q k^T / sqrt(dk))) + raw row sums
    dim3 g2(S / NT, S / MT, NH);
    kQKT<<<g2, blk, H_SMEM>>>(q, k, eh, nullptr, nullptr, rs,
                              DK, H, H, S,
                              (long long)DK, (long long)DK, (long long)S * S,
                              inv_sqrt_dk, S);

    // 3) AV (fp16): Y = tf32((E @ vt^T)/rs); writes fp32 normalized attn
    dim3 g3(DK / NT, S / MT, NH);
    kAV<<<g3, blk, H_SMEM>>>(eh, vt, nullptr, y, attn_out, rs,
                             S, S, S, H,
                             (long long)S * S, (long long)DK * S, (long long)DK,
                             1.0f, S);

    // 4) output projection (tf32): y_out = Y @ Wo
    dim3 g4(F / NT, S / MT, 1);
    kPROJ<<<g4, blk, SMEM_DYN>>>(y, Wo, nullptr, nullptr, y_out, nullptr, nullptr, rs,
                                 H, H, F, F, 0, 1.0f, S);
}

// round 17
// speedup vs baseline: 1.3835x; 1.1462x over previous
#include <cuda_runtime.h>
#include <cuda_fp16.h>
#include <cstdint>
#include <math.h>

// ---------------------------------------------------------------------------
// MultiHeadAttention, all-fp16 m16n8k16 mma pipeline (fp32 accumulate).
// Inputs pre-converted to fp16 (x flat; W transposed to K-major) by two
// small kernels. All GEMMs: TB all-ldsm form, CTA 128x128x32, 4 warps,
// 64x64 warp tiles, cp.async 3-stage, 2 CTAs/SM.
// Pipeline: cvt -> QKV(fused, fp16 out, v transposed) ->
//           QKT(exp epilogue, fp16 E + rowsums) ->
//           AV(normalize attn writeback fp32, fp16 Y) -> PROJ(fp32 out).
// d_out = y [S,F] then attn [8,S,S] (fp32). S=4096, F=H=1024, dk=128.
// ---------------------------------------------------------------------------

#define SMAX 4096
#define HMAX 1024
#define NHEAD 8

__device__ __half g_x16[SMAX * HMAX];                    // x fp16 [S][F]
__device__ __half g_wt[4 * HMAX * HMAX];                 // WqT|WkT|WvT|WoT fp16
__device__ __half g_qk[2 * SMAX * HMAX];                 // q | k fp16 [S][H]
__device__ __half g_vt[HMAX * SMAX];                     // v^T fp16 [H][S]
__device__ __half g_eh[(size_t)NHEAD * SMAX * SMAX];     // raw exp fp16
__device__ __half g_y16[SMAX * HMAX];                    // Y fp16 [S][H]
__device__ float  g_rs[NHEAD * SMAX];                    // raw row sums

__device__ __forceinline__ void mma_f16(float* c, const unsigned* a, const unsigned* b) {
    asm volatile(
        "mma.sync.aligned.m16n8k16.row.col.f32.f16.f16.f32 "
        "{%0,%1,%2,%3}, {%4,%5,%6,%7}, {%8,%9}, {%0,%1,%2,%3};"
        : "+f"(c[0]), "+f"(c[1]), "+f"(c[2]), "+f"(c[3])
        : "r"(a[0]), "r"(a[1]), "r"(a[2]), "r"(a[3]), "r"(b[0]), "r"(b[1]));
}
__device__ __forceinline__ void ldsm4(unsigned* r, uint32_t a) {
    asm volatile("ldmatrix.sync.aligned.m8n8.x4.shared.b16 {%0,%1,%2,%3}, [%4];"
        : "=r"(r[0]), "=r"(r[1]), "=r"(r[2]), "=r"(r[3]) : "r"(a));
}
__device__ __forceinline__ uint32_t smem_u32(const void* p) {
    uint32_t a;
    asm("{ .reg .u64 t; cvta.to.shared.u64 t, %1; cvt.u32.u64 %0, t; }" : "=r"(a) : "l"(p));
    return a;
}
__device__ __forceinline__ void cp16(uint32_t s, const void* g) {
    asm volatile("cp.async.cg.shared.global [%0], [%1], 16;" :: "r"(s), "l"(g));
}
#define CP_COMMIT() asm volatile("cp.async.commit_group;")
#define CP_WAIT1()  asm volatile("cp.async.wait_group 1;")
#define CP_WAIT0()  asm volatile("cp.async.wait_group 0;")

#define STAGES 3
#define HSB 80                      // fp16 tile row stride bytes (40 halves)
#define H_TILE (128 * HSB)          // 10240
#define H_STAGE (2 * H_TILE)        // 20480
#define H_SMEM (STAGES * H_STAGE)   // 61440

// ---------------------------------------------------------------------------
// fp16 TB GEMM: C = alpha * A[M,K] @ B[rows=N][K]^T, both fp16 K-major.
// EXPE : Ce = fp16(exp(alpha*acc)), atomicAdd fp32 row sums into rs
// NORM : A tiles are raw E; landed tiles re-read from smem, scaled by 1/rs,
//        written fp32 to Aw (final attn); epilogue scales rows by 1/rs.
// QKV3 : blockIdx.x = (bsel<<3)|ntile; bsel<2 -> fp16 rows into Ce + bsel*sC;
//        bsel==2 -> fp16 transposed into VT16 [N-dim][S]. x==0 CTAs zero rs.
// OUT16: plain epilogue writes fp16 to Ce (else fp32 to Cf, final output).
// ---------------------------------------------------------------------------
template <bool EXPE, bool NORM, bool QKV3, bool OUT16>
__global__ void __launch_bounds__(128, 2) gemm_h16(
    const __half* __restrict__ A, const __half* __restrict__ B0,
    const __half* __restrict__ B1, const __half* __restrict__ B2,
    __half* __restrict__ Ce, float* __restrict__ Cf, __half* __restrict__ VT16,
    float* __restrict__ Aw, float* __restrict__ rs,
    int K, int lda, int ldb, int ldc,
    long long sA, long long sB, long long sC, float alpha, int S)
{
    extern __shared__ char smem[];
    const uint32_t sbase = smem_u32(smem);
    const int tid = threadIdx.x;
    const int lane = tid & 31;
    const int warp = tid >> 5;
    const int lg = lane >> 2;
    const int l4 = lane & 3;
    const int wm = (warp & 1) * 64;
    const int wn = (warp >> 1) * 64;
    const int lgp = lane >> 3, ri = lane & 7;
    const uint32_t aoffh = (uint32_t)((wm + ((lgp & 1) << 3) + ri) * HSB + ((lgp >> 1) << 4));
    const uint32_t boffh = (uint32_t)((wn + ((lgp & 1) << 3) + ri) * HSB + ((lgp >> 1) << 4));

    const int m0 = blockIdx.y * 128;
    const int z = blockIdx.z;
    int n0, bsel = 0;
    const __half* B;
    if (QKV3) {
        bsel = blockIdx.x >> 3;
        n0 = (blockIdx.x & 7) * 128;
        B = (bsel == 0) ? B0 : ((bsel == 1) ? B1 : B2);
        if (blockIdx.x == 0) {
            float4 zz = make_float4(0.f, 0.f, 0.f, 0.f);
            float* p = rs + blockIdx.y * (NHEAD * S / 32) + tid * 8;
            *(float4*)p = zz;
            *(float4*)(p + 4) = zz;
        }
    } else {
        n0 = blockIdx.x * 128;
        B = B0;
    }

    const __half* Ab = A + (long long)z * sA + (long long)m0 * lda;
    const __half* Bb = B + (long long)z * sB + (long long)n0 * ldb;
    __half* Cbe = nullptr;
    float* Cbf = nullptr;
    if (QKV3) {
        if (bsel < 2) Cbe = Ce + (long long)bsel * sC + (long long)m0 * ldc + n0;
    } else if (EXPE || OUT16) {
        Cbe = Ce + (long long)z * sC + (long long)m0 * ldc + n0;
    } else {
        Cbf = Cf + (long long)z * sC + (long long)m0 * ldc + n0;
    }
    float* Awb = NORM ? (Aw + (long long)z * (long long)S * S + (long long)m0 * lda) : nullptr;

    const int row2 = tid >> 2;          // 0..31 (+32i)
    const int chk  = tid & 3;           // 16B chunk within 64B row

    float inv[4];
    if (NORM) {
#pragma unroll
        for (int i = 0; i < 4; i++)
            inv[i] = 1.0f / rs[z * S + m0 + row2 + 32 * i];
    }

    float acc[4][8][4];
#pragma unroll
    for (int mt = 0; mt < 4; mt++)
#pragma unroll
        for (int nt = 0; nt < 8; nt++)
#pragma unroll
            for (int i = 0; i < 4; i++) acc[mt][nt][i] = 0.0f;

    const int ktiles = K / 32;

    auto issueA = [&](int st, int kt) {
        const uint32_t as = sbase + st * H_STAGE;
        const __half* p = Ab + (long long)row2 * lda + kt * 32 + chk * 8;
#pragma unroll
        for (int i = 0; i < 4; i++)
            cp16(as + (uint32_t)((row2 + 32 * i) * HSB + chk * 16),
                 p + (long long)(32 * i) * lda);
    };
    auto issueB = [&](int st, int kt) {
        const uint32_t bs = sbase + st * H_STAGE + H_TILE;
        const __half* p = Bb + (long long)row2 * ldb + kt * 32 + chk * 8;
#pragma unroll
        for (int i = 0; i < 4; i++)
            cp16(bs + (uint32_t)((row2 + 32 * i) * HSB + chk * 16),
                 p + (long long)(32 * i) * ldb);
    };
    auto wrNorm = [&](int st, int kt) {
        const char* As = smem + st * H_STAGE;
#pragma unroll
        for (int i = 0; i < 4; i++) {
            const int row = row2 + 32 * i;
            const __half2* h = (const __half2*)(As + row * HSB + chk * 16);
            float* d = Awb + (long long)row * lda + kt * 32 + chk * 8;
            float4 v0, v1;
            float2 t;
            t = __half22float2(h[0]); v0.x = t.x * inv[i]; v0.y = t.y * inv[i];
            t = __half22float2(h[1]); v0.z = t.x * inv[i]; v0.w = t.y * inv[i];
            t = __half22float2(h[2]); v1.x = t.x * inv[i]; v1.y = t.y * inv[i];
            t = __half22float2(h[3]); v1.z = t.x * inv[i]; v1.w = t.y * inv[i];
            *(float4*)d = v0;
            *(float4*)(d + 4) = v1;
        }
    };

#pragma unroll
    for (int s = 0; s < 2; s++) {
        issueA(s, s);
        issueB(s, s);
        CP_COMMIT();
    }

    for (int kt = 0; kt < ktiles; kt++) {
        const int cur = kt % STAGES;
        const bool has = (kt + 2 < ktiles);
        if (has) CP_WAIT1(); else CP_WAIT0();
        __syncthreads();

        const int nx = (kt + 2) % STAGES;
        if (has) {
            issueA(nx, kt + 2);
            issueB(nx, kt + 2);
            CP_COMMIT();
        }

        if (NORM) wrNorm(cur, kt);

        const uint32_t as_s = sbase + cur * H_STAGE;
        const uint32_t bs_s = as_s + H_TILE;

#pragma unroll
        for (int ks = 0; ks < 2; ks++) {   // two k16 steps per BK=32
            unsigned af[4][4], bf[8][2];
#pragma unroll
            for (int mt = 0; mt < 4; mt++)
                ldsm4(af[mt], as_s + aoffh + (uint32_t)(mt * 16 * HSB + ks * 32));
#pragma unroll
            for (int np = 0; np < 4; np++) {
                unsigned r[4];
                ldsm4(r, bs_s + boffh + (uint32_t)(np * 16 * HSB + ks * 32));
                bf[2 * np][0]     = r[0];
                bf[2 * np + 1][0] = r[1];
                bf[2 * np][1]     = r[2];
                bf[2 * np + 1][1] = r[3];
            }
#pragma unroll
            for (int mt = 0; mt < 4; mt++)
#pragma unroll
                for (int nt = 0; nt < 8; nt++)
                    mma_f16(acc[mt][nt], af[mt], bf[nt]);
        }
    }

    // ---- epilogue ----
    if (EXPE) {
        float ps[4][2];
#pragma unroll
        for (int mt = 0; mt < 4; mt++) { ps[mt][0] = 0.0f; ps[mt][1] = 0.0f; }
#pragma unroll
        for (int mt = 0; mt < 4; mt++) {
            const int r = wm + mt * 16 + lg;
#pragma unroll
            for (int nt = 0; nt < 8; nt++) {
                const int c = wn + nt * 8 + 2 * l4;
                __half2 h01 = __floats2half2_rn(__expf(acc[mt][nt][0] * alpha),
                                                __expf(acc[mt][nt][1] * alpha));
                __half2 h23 = __floats2half2_rn(__expf(acc[mt][nt][2] * alpha),
                                                __expf(acc[mt][nt][3] * alpha));
                *(__half2*)(Cbe + (long long)r * ldc + c) = h01;
                *(__half2*)(Cbe + (long long)(r + 8) * ldc + c) = h23;
                float2 f01 = __half22float2(h01);
                float2 f23 = __half22float2(h23);
                ps[mt][0] += f01.x + f01.y;
                ps[mt][1] += f23.x + f23.y;
            }
        }
#pragma unroll
        for (int mt = 0; mt < 4; mt++) {
#pragma unroll
            for (int h = 0; h < 2; h++) {
                float v = ps[mt][h];
                v += __shfl_xor_sync(0xffffffffu, v, 1);
                v += __shfl_xor_sync(0xffffffffu, v, 2);
                if (l4 == 0)
                    atomicAdd(&rs[z * S + m0 + wm + mt * 16 + lg + h * 8], v);
            }
        }
    } else {
#pragma unroll
        for (int mt = 0; mt < 4; mt++) {
            const int r = wm + mt * 16 + lg;
            const float s0 = NORM ? 1.0f / rs[z * S + m0 + r] : alpha;
            const float s1 = NORM ? 1.0f / rs[z * S + m0 + r + 8] : alpha;
#pragma unroll
            for (int nt = 0; nt < 8; nt++) {
                const int c = wn + nt * 8 + 2 * l4;
                float o0 = acc[mt][nt][0] * s0, o1 = acc[mt][nt][1] * s0;
                float o2 = acc[mt][nt][2] * s1, o3 = acc[mt][nt][3] * s1;
                if (OUT16) {
                    if (QKV3 && bsel == 2) {
                        const long long gm = m0 + r;
                        const int gc = n0 + c;
                        VT16[(long long)gc * S + gm]           = __float2half_rn(o0);
                        VT16[(long long)(gc + 1) * S + gm]     = __float2half_rn(o1);
                        VT16[(long long)gc * S + gm + 8]       = __float2half_rn(o2);
                        VT16[(long long)(gc + 1) * S + gm + 8] = __float2half_rn(o3);
                    } else {
                        *(__half2*)(Cbe + (long long)r * ldc + c) = __floats2half2_rn(o0, o1);
                        *(__half2*)(Cbe + (long long)(r + 8) * ldc + c) = __floats2half2_rn(o2, o3);
                    }
                } else {
                    *(float2*)(Cbf + (long long)r * ldc + c) = make_float2(o0, o1);
                    *(float2*)(Cbf + (long long)(r + 8) * ldc + c) = make_float2(o2, o3);
                }
            }
        }
    }
}

// x -> fp16 flat convert + rs zeroing
__global__ void cvt_x_rs(const float* __restrict__ x, __half* __restrict__ x16,
                         float* __restrict__ rs, int n)
{
    const int base = (blockIdx.x * 256 + threadIdx.x) * 4;
    if (base < n) {
        float4 v = *(const float4*)(x + base);
        __half2* d = (__half2*)(x16 + base);
        d[0] = __floats2half2_rn(v.x, v.y);
        d[1] = __floats2half2_rn(v.z, v.w);
    }
    if (blockIdx.x < 32) {
        float* p = rs + blockIdx.x * 1024 + threadIdx.x * 4;
        *(float4*)p = make_float4(0.f, 0.f, 0.f, 0.f);
    }
}

// W [N][N] fp32 -> transposed fp16 [N][N]; blockIdx.z selects matrix.
__global__ void wtrans(const float* __restrict__ W0, const float* __restrict__ W1,
                       const float* __restrict__ W2, const float* __restrict__ W3,
                       __half* __restrict__ T0, __half* __restrict__ T1,
                       __half* __restrict__ T2, __half* __restrict__ T3, int N)
{
    const float* W = (blockIdx.z == 0) ? W0 : (blockIdx.z == 1) ? W1
                     : (blockIdx.z == 2) ? W2 : W3;
    __half* T = (blockIdx.z == 0) ? T0 : (blockIdx.z == 1) ? T1
                : (blockIdx.z == 2) ? T2 : T3;
    __shared__ float t[32][33];
    const int x = blockIdx.x * 32 + threadIdx.x;
    const int y0 = blockIdx.y * 32 + threadIdx.y;
#pragma unroll
    for (int j = 0; j < 4; j++)
        t[threadIdx.y + 8 * j][threadIdx.x] = W[(long long)(y0 + 8 * j) * N + x];
    __syncthreads();
    const int ox = blockIdx.y * 32 + threadIdx.x;
    const int oy0 = blockIdx.x * 32 + threadIdx.y;
#pragma unroll
    for (int j = 0; j < 4; j++)
        T[(long long)(oy0 + 8 * j) * N + ox] =
            __float2half_rn(t[threadIdx.x][threadIdx.y + 8 * j]);
}

extern "C" void kernel_launch(void* const* d_in, const int* in_sizes, int n_in,
                              void* d_out, int out_size)
{
    const float* x  = (const float*)d_in[0];
    const float* Wq = (const float*)d_in[1];
    const float* Wk = (const float*)d_in[2];
    const float* Wv = (const float*)d_in[3];
    const float* Wo = (const float*)d_in[4];

    const int F  = 1024;
    const int H  = 1024;
    const int NH = NHEAD;
    const int DK = H / NH;
    const int S  = in_sizes[0] / F;

    float* y_out    = (float*)d_out;
    float* attn_out = y_out + (long long)S * H;

    __half *x16, *wt, *qk, *vt, *eh, *y16;
    float *rs;
    cudaGetSymbolAddress((void**)&x16, g_x16);
    cudaGetSymbolAddress((void**)&wt, g_wt);
    cudaGetSymbolAddress((void**)&qk, g_qk);
    cudaGetSymbolAddress((void**)&vt, g_vt);
    cudaGetSymbolAddress((void**)&eh, g_eh);
    cudaGetSymbolAddress((void**)&y16, g_y16);
    cudaGetSymbolAddress((void**)&rs, g_rs);
    __half* q = qk;
    __half* k = qk + (long long)S * H;
    __half* wtq = wt;
    __half* wtk = wt + (long long)H * H;
    __half* wtv = wt + 2LL * H * H;
    __half* wto = wt + 3LL * H * H;

    // template args: EXPE, NORM, QKV3, OUT16
    auto kQKV  = gemm_h16<false, false, true,  true >;
    auto kQKT  = gemm_h16<true,  false, false, false>;
    auto kAV   = gemm_h16<false, true,  false, true >;
    auto kPROJ = gemm_h16<false, false, false, false>;

    cudaFuncSetAttribute(kQKV,  cudaFuncAttributeMaxDynamicSharedMemorySize, H_SMEM);
    cudaFuncSetAttribute(kQKT,  cudaFuncAttributeMaxDynamicSharedMemorySize, H_SMEM);
    cudaFuncSetAttribute(kAV,   cudaFuncAttributeMaxDynamicSharedMemorySize, H_SMEM);
    cudaFuncSetAttribute(kPROJ, cudaFuncAttributeMaxDynamicSharedMemorySize, H_SMEM);

    const dim3 blk(128);
    const float inv_sqrt_dk = 0.08838834764831845f;  // 1/sqrt(128)

    // 0) convert x -> fp16 (+zero rs); transpose-convert weights -> fp16
    cvt_x_rs<<<(S * F) / 1024, 256>>>(x, x16, rs, S * F);
    wtrans<<<dim3(H / 32, H / 32, 4), dim3(32, 8)>>>(Wq, Wk, Wv, Wo,
                                                     wtq, wtk, wtv, wto, H);

    // 1) fused Q/K/V projections (fp16 in/out; v transposed); rs zeroed again
    dim3 g1(3 * (H / 128), S / 128, 1);
    kQKV<<<g1, blk, H_SMEM>>>(x16, wtq, wtk, wtv, qk, nullptr, vt, nullptr, rs,
                              F, F, F, H,
                              0, 0, (long long)S * H, 1.0f, S);

    // 2) QKT: E = fp16(exp(q k^T / sqrt(dk))) + raw row sums
    dim3 g2(S / 128, S / 128, NH);
    kQKT<<<g2, blk, H_SMEM>>>(q, k, nullptr, nullptr, eh, nullptr, nullptr,
                              nullptr, rs,
                              DK, H, H, S,
                              (long long)DK, (long long)DK, (long long)S * S,
                              inv_sqrt_dk, S);

    // 3) AV: Y16 = fp16((E @ vt^T)/rs); writes fp32 normalized attn from smem
    dim3 g3(DK / 128, S / 128, NH);
    kAV<<<g3, blk, H_SMEM>>>(eh, vt, nullptr, nullptr, y16, nullptr, nullptr,
                             attn_out, rs,
                             S, S, S, H,
                             (long long)S * S, (long long)DK * S, (long long)DK,
                             1.0f, S);

    // 4) output projection: y_out = Y16 @ WoT^T (fp32 out)
    dim3 g4(F / 128, S / 128, 1);
    kPROJ<<<g4, blk, H_SMEM>>>(y16, wto, nullptr, nullptr, nullptr, y_out,
                               nullptr, nullptr, rs,
                               H, H, H, F,
                               0, 0, 0, 1.0f, S);
}